// round 11
// baseline (speedup 1.0000x reference)
#include <cuda_runtime.h>
#include <cuda_fp16.h>

#define BB 2
#define SS 2048
#define DD 1024
#define HH 16
#define DK 64

// Scratch (allocation-free: __device__ globals)
__device__ __half g_xh[(size_t)BB * SS * DD];
__device__ __half g_wh[4 * (size_t)DD * DD];   // Wq,Wk,Wv,Wo fp16
__device__ __half g_q[(size_t)BB * SS * DD];   // pre-scaled by 0.125*log2(e)
__device__ __half g_k[(size_t)BB * SS * DD];
__device__ __half g_v[(size_t)BB * SS * DD];
__device__ __half g_ctx[(size_t)BB * SS * DD];
__device__ float  g_po[(size_t)BB * SS * DD];
__device__ float  g_attn[(size_t)BB * HH * SS * SS];

#define EXS 0.18033688011112043f  /* 0.125 * log2(e) */

__device__ __forceinline__ void mma_fp16(float* c, const unsigned* a, unsigned b0, unsigned b1) {
    asm volatile(
        "mma.sync.aligned.m16n8k16.row.col.f32.f16.f16.f32 "
        "{%0,%1,%2,%3}, {%4,%5,%6,%7}, {%8,%9}, {%0,%1,%2,%3};\n"
        : "+f"(c[0]), "+f"(c[1]), "+f"(c[2]), "+f"(c[3])
        : "r"(a[0]), "r"(a[1]), "r"(a[2]), "r"(a[3]), "r"(b0), "r"(b1));
}

__device__ __forceinline__ void ldsm4(unsigned* r, unsigned addr) {
    asm volatile("ldmatrix.sync.aligned.m8n8.x4.shared.b16 {%0,%1,%2,%3}, [%4];"
                 : "=r"(r[0]), "=r"(r[1]), "=r"(r[2]), "=r"(r[3]) : "r"(addr));
}

__device__ __forceinline__ void ldsm4t(unsigned* r, unsigned addr) {
    asm volatile("ldmatrix.sync.aligned.m8n8.x4.trans.shared.b16 {%0,%1,%2,%3}, [%4];"
                 : "=r"(r[0]), "=r"(r[1]), "=r"(r[2]), "=r"(r[3]) : "r"(addr));
}

#define CP_A16(dst, src) asm volatile("cp.async.cg.shared.global [%0], [%1], 16;\n" :: "r"(dst), "l"(src))
#define CP_COMMIT()      asm volatile("cp.async.commit_group;\n")
#define CP_WAIT0()       asm volatile("cp.async.wait_group 0;\n")

// ---------------------------------------------------------------------------
// Combined fp32 -> fp16 converter: x (n4x float4s) then 4 weights (n4w each).
// ---------------------------------------------------------------------------
#define N4X ((int)((size_t)BB * SS * DD / 4))
#define N4W ((int)((size_t)DD * DD / 4))

__global__ __launch_bounds__(256) void f2h_multi(
    const float4* __restrict__ x,  const float4* __restrict__ wq,
    const float4* __restrict__ wk, const float4* __restrict__ wv,
    const float4* __restrict__ wo, uint2* __restrict__ xh, uint2* __restrict__ wh)
{
    const int i = blockIdx.x * 256 + threadIdx.x;
    const float4* src;
    uint2* dst;
    int off;
    if (i < N4X) {
        src = x; dst = xh; off = i;
    } else {
        const int j = i - N4X;
        const int seg = j / N4W;
        off = j - seg * N4W;
        src = (seg == 0) ? wq : (seg == 1) ? wk : (seg == 2) ? wv : wo;
        dst = wh + (size_t)seg * N4W;
    }
    const float4 v = src[off];
    __half2 h0 = __floats2half2_rn(v.x, v.y);
    __half2 h1 = __floats2half2_rn(v.z, v.w);
    dst[off] = make_uint2(*(unsigned*)&h0, *(unsigned*)&h1);
}

// ===========================================================================
// Attention kernel. Q pre-scaled so p = exp2(QK). h2exp2 f16x2 exp path.
// 64 q rows / CTA, 256 threads (8 warps 2x4), 2 CTAs/SM, cp.async pipelined.
// ===========================================================================
#define QSP 72
#define KSP 72
#define VSP 72
#define PSP 136

#define SM_QS 0
#define SM_K0 4608
#define KTILE 9216
#define SM_V0 (SM_K0 + 2 * KTILE)
#define SM_PS (SM_V0 + 2 * KTILE)
#define SM_ENDH (SM_PS + 64 * PSP)
#define SM_BYTES (SM_ENDH * 2 + 64 * 4)

template <bool WRITE_ATTN>
__global__ __launch_bounds__(256, 2) void attn_kernel(
    const __half* __restrict__ q, const __half* __restrict__ k,
    const __half* __restrict__ v, float* __restrict__ attn,
    __half* __restrict__ ctx)
{
    extern __shared__ __half smh[];
    __half* Ps = smh + SM_PS;
    float* rs  = (float*)(smh + SM_ENDH);

    const unsigned smu = (unsigned)__cvta_generic_to_shared(smh);
    const unsigned QsU = smu + SM_QS * 2;
    const unsigned KsU = smu + SM_K0 * 2;
    const unsigned VsU = smu + SM_V0 * 2;
    const unsigned PsU = smu + SM_PS * 2;

    const int z = blockIdx.y;
    const int b = z >> 4, h = z & 15;
    const size_t base = (size_t)b * SS * DD + (size_t)h * DK;
    const int q0 = blockIdx.x * 64;

    const __half* qp = q + base + (size_t)q0 * DD;
    const __half* kp = k + base;
    const __half* vp = v + base;
    float* attp = attn + (size_t)z * SS * SS + (size_t)q0 * SS;

    const int tid = threadIdx.x;
    const int warp = tid >> 5, l = tid & 31;
    const int gid = l >> 2, tig = l & 3;
    const int wm = warp >> 2, wn = warp & 3;

    const int arow  = (l & 7) + ((l >> 3) & 1) * 8;
    const int acolh = (l >> 4) * 8;

    const int crow0 = tid >> 3, cch = (tid & 7) * 8;

    // prefetch Q + K tile 0
    #pragma unroll
    for (int i = 0; i < 2; i++) {
        const int row = crow0 + i * 32;
        CP_A16(QsU + (row * QSP + cch) * 2, qp + (size_t)row * DD + cch);
    }
    #pragma unroll
    for (int i = 0; i < 4; i++) {
        const int row = crow0 + i * 32;
        CP_A16(KsU + (row * KSP + cch) * 2, kp + (size_t)row * DD + cch);
    }
    CP_COMMIT();
    if (tid < 64) rs[tid] = 0.f;

    float rsum[2][2] = {};

    // =================== PASS 1: row sums (1 sync/tile) ===================
    for (int kt = 0; kt < SS / 128; kt++) {
        CP_WAIT0();
        __syncthreads();
        if (kt < 15) {
            const unsigned kb = KsU + ((kt + 1) & 1) * KTILE * 2;
            #pragma unroll
            for (int i = 0; i < 4; i++) {
                const int row = crow0 + i * 32;
                CP_A16(kb + (row * KSP + cch) * 2, kp + (size_t)((kt + 1) * 128 + row) * DD + cch);
            }
            CP_COMMIT();
        }

        const unsigned kcur = KsU + (kt & 1) * KTILE * 2;
        float c[2][4][4] = {};
        #pragma unroll
        for (int kk = 0; kk < DK; kk += 16) {
            unsigned af[2][4], bf[2][4];
            ldsm4(af[0], QsU + ((wm * 32 + arow) * QSP + kk + acolh) * 2);
            ldsm4(af[1], QsU + ((wm * 32 + 16 + arow) * QSP + kk + acolh) * 2);
            ldsm4(bf[0], kcur + ((wn * 32 + arow) * KSP + kk + acolh) * 2);
            ldsm4(bf[1], kcur + ((wn * 32 + 16 + arow) * KSP + kk + acolh) * 2);
            #pragma unroll
            for (int mt = 0; mt < 2; mt++) {
                mma_fp16(c[mt][0], af[mt], bf[0][0], bf[0][2]);
                mma_fp16(c[mt][1], af[mt], bf[0][1], bf[0][3]);
                mma_fp16(c[mt][2], af[mt], bf[1][0], bf[1][2]);
                mma_fp16(c[mt][3], af[mt], bf[1][1], bf[1][3]);
            }
        }
        #pragma unroll
        for (int mt = 0; mt < 2; mt++)
            #pragma unroll
            for (int nt = 0; nt < 4; nt++) {
                const __half2 e0 = h2exp2(__floats2half2_rn(c[mt][nt][0], c[mt][nt][1]));
                const __half2 e1 = h2exp2(__floats2half2_rn(c[mt][nt][2], c[mt][nt][3]));
                const float2 f0 = __half22float2(e0);
                const float2 f1 = __half22float2(e1);
                rsum[mt][0] += f0.x + f0.y;
                rsum[mt][1] += f1.x + f1.y;
            }
    }

    #pragma unroll
    for (int mt = 0; mt < 2; mt++)
        #pragma unroll
        for (int hf = 0; hf < 2; hf++) {
            float v0 = rsum[mt][hf];
            v0 += __shfl_xor_sync(0xffffffffu, v0, 1);
            v0 += __shfl_xor_sync(0xffffffffu, v0, 2);
            if (tig == 0) atomicAdd(&rs[wm * 32 + mt * 16 + hf * 8 + gid], v0);
        }
    __syncthreads();

    __half2 inv2[2][2];
    #pragma unroll
    for (int mt = 0; mt < 2; mt++)
        #pragma unroll
        for (int hf = 0; hf < 2; hf++)
            inv2[mt][hf] = __float2half2_rn(1.0f / rs[wm * 32 + mt * 16 + hf * 8 + gid]);

    float cacc[2][2][4] = {};

    // prefetch K+V tile 0 for pass 2 (ordered by the sync above)
    #pragma unroll
    for (int i = 0; i < 4; i++) {
        const int row = crow0 + i * 32;
        CP_A16(KsU + (row * KSP + cch) * 2, kp + (size_t)row * DD + cch);
        CP_A16(VsU + (row * VSP + cch) * 2, vp + (size_t)row * DD + cch);
    }
    CP_COMMIT();

    // =================== PASS 2 (2 syncs/tile) ===================
    for (int kt = 0; kt < SS / 128; kt++) {
        CP_WAIT0();
        __syncthreads();
        if (kt < 15) {
            const unsigned kb = KsU + ((kt + 1) & 1) * KTILE * 2;
            const unsigned vb = VsU + ((kt + 1) & 1) * KTILE * 2;
            #pragma unroll
            for (int i = 0; i < 4; i++) {
                const int row = crow0 + i * 32;
                CP_A16(kb + (row * KSP + cch) * 2, kp + (size_t)((kt + 1) * 128 + row) * DD + cch);
                CP_A16(vb + (row * VSP + cch) * 2, vp + (size_t)((kt + 1) * 128 + row) * DD + cch);
            }
            CP_COMMIT();
        }

        const unsigned kcur = KsU + (kt & 1) * KTILE * 2;
        const unsigned vcur = VsU + (kt & 1) * KTILE * 2;

        float c[2][4][4] = {};
        #pragma unroll
        for (int kk = 0; kk < DK; kk += 16) {
            unsigned af[2][4], bf[2][4];
            ldsm4(af[0], QsU + ((wm * 32 + arow) * QSP + kk + acolh) * 2);
            ldsm4(af[1], QsU + ((wm * 32 + 16 + arow) * QSP + kk + acolh) * 2);
            ldsm4(bf[0], kcur + ((wn * 32 + arow) * KSP + kk + acolh) * 2);
            ldsm4(bf[1], kcur + ((wn * 32 + 16 + arow) * KSP + kk + acolh) * 2);
            #pragma unroll
            for (int mt = 0; mt < 2; mt++) {
                mma_fp16(c[mt][0], af[mt], bf[0][0], bf[0][2]);
                mma_fp16(c[mt][1], af[mt], bf[0][1], bf[0][3]);
                mma_fp16(c[mt][2], af[mt], bf[1][0], bf[1][2]);
                mma_fp16(c[mt][3], af[mt], bf[1][1], bf[1][3]);
            }
        }

        // exp2 (f16x2) -> normalize (HMUL2) -> stage fp16 P
        #pragma unroll
        for (int mt = 0; mt < 2; mt++) {
            const int r0 = wm * 32 + mt * 16 + gid;
            #pragma unroll
            for (int nt = 0; nt < 4; nt++) {
                const int cl = wn * 32 + nt * 8 + 2 * tig;
                const __half2 p0 = __hmul2(h2exp2(__floats2half2_rn(c[mt][nt][0], c[mt][nt][1])), inv2[mt][0]);
                const __half2 p1 = __hmul2(h2exp2(__floats2half2_rn(c[mt][nt][2], c[mt][nt][3])), inv2[mt][1]);
                *(unsigned*)&Ps[r0 * PSP + cl]       = *(const unsigned*)&p0;
                *(unsigned*)&Ps[(r0 + 8) * PSP + cl] = *(const unsigned*)&p1;
            }
        }
        __syncthreads();

        // ctx += P @ V
        #pragma unroll
        for (int kk = 0; kk < 128; kk += 16) {
            unsigned af[2][4], bf[4];
            ldsm4(af[0], PsU + ((wm * 32 + arow) * PSP + kk + acolh) * 2);
            ldsm4(af[1], PsU + ((wm * 32 + 16 + arow) * PSP + kk + acolh) * 2);
            ldsm4t(bf, vcur + ((kk + arow) * VSP + wn * 16 + acolh) * 2);
            #pragma unroll
            for (int mt = 0; mt < 2; mt++) {
                mma_fp16(cacc[mt][0], af[mt], bf[0], bf[1]);
                mma_fp16(cacc[mt][1], af[mt], bf[2], bf[3]);
            }
        }

        if (WRITE_ATTN) {
            #pragma unroll
            for (int i = 0; i < 8; i++) {
                const int idx = tid + i * 256;
                const int row = idx >> 5, c4 = idx & 31;
                const uint2 hraw = *(const uint2*)&Ps[row * PSP + c4 * 4];
                const float2 f01 = __half22float2(*(const __half2*)&hraw.x);
                const float2 f23 = __half22float2(*(const __half2*)&hraw.y);
                *(float4*)(attp + (size_t)row * SS + kt * 128 + c4 * 4) =
                    make_float4(f01.x, f01.y, f23.x, f23.y);
            }
        }
    }

    __syncthreads();
    __half* cp = ctx + base + (size_t)q0 * DD;
    #pragma unroll
    for (int mt = 0; mt < 2; mt++) {
        const int r0 = wm * 32 + mt * 16 + gid;
        #pragma unroll
        for (int nt = 0; nt < 2; nt++) {
            const int cl = wn * 16 + nt * 8 + 2 * tig;
            __half2 h0 = __floats2half2_rn(cacc[mt][nt][0], cacc[mt][nt][1]);
            __half2 h1 = __floats2half2_rn(cacc[mt][nt][2], cacc[mt][nt][3]);
            *(unsigned*)(cp + (size_t)r0 * DD + cl)       = *(unsigned*)&h0;
            *(unsigned*)(cp + (size_t)(r0 + 8) * DD + cl) = *(unsigned*)&h1;
        }
    }
}

// ===========================================================================
// Projection GEMM, all-fp16 operands, cp.async pipelined (1 sync/iter).
// C = A @ B^T, 128x128x64 tile, 256 threads (8 warps 4x2), 2 CTAs/SM.
// SCALE: multiply output by EXS (Q projection).
// ===========================================================================
#define GSP 72
#define GTILE (128 * GSP)
#define GEMM_SMEM_BYTES (4 * GTILE * 2)

template <bool CH, bool SCALE>
__global__ __launch_bounds__(256, 2) void gemm_h(
    const __half* __restrict__ A, const __half* __restrict__ Bm, void* __restrict__ Cp)
{
    extern __shared__ __half gsm[];
    const unsigned smu = (unsigned)__cvta_generic_to_shared(gsm);
    const unsigned AsU = smu;
    const unsigned BsU = smu + 2 * GTILE * 2;

    const int tid = threadIdx.x;
    const int warp = tid >> 5, l = tid & 31;
    const int gid = l >> 2, tig = l & 3;
    const int wm = warp >> 1, wn = warp & 1;
    const int m0 = blockIdx.y * 128;
    const int n0 = blockIdx.x * 128;

    const int arow  = (l & 7) + ((l >> 3) & 1) * 8;
    const int acolh = (l >> 4) * 8;

    const int crow0 = tid >> 3, cch = (tid & 7) * 8;

    float acc[2][8][4] = {};

    #pragma unroll
    for (int i = 0; i < 4; i++) {
        const int row = crow0 + i * 32;
        CP_A16(AsU + (row * GSP + cch) * 2, A  + (size_t)(m0 + row) * DD + cch);
        CP_A16(BsU + (row * GSP + cch) * 2, Bm + (size_t)(n0 + row) * DD + cch);
    }
    CP_COMMIT();

    for (int it = 0; it < DD / 64; it++) {
        CP_WAIT0();
        __syncthreads();
        if (it < DD / 64 - 1) {
            const unsigned ab = AsU + ((it + 1) & 1) * GTILE * 2;
            const unsigned bb = BsU + ((it + 1) & 1) * GTILE * 2;
            const int k0 = (it + 1) * 64;
            #pragma unroll
            for (int i = 0; i < 4; i++) {
                const int row = crow0 + i * 32;
                CP_A16(ab + (row * GSP + cch) * 2, A  + (size_t)(m0 + row) * DD + k0 + cch);
                CP_A16(bb + (row * GSP + cch) * 2, Bm + (size_t)(n0 + row) * DD + k0 + cch);
            }
            CP_COMMIT();
        }

        const unsigned acur = AsU + (it & 1) * GTILE * 2;
        const unsigned bcur = BsU + (it & 1) * GTILE * 2;

        #pragma unroll
        for (int kk = 0; kk < 64; kk += 16) {
            unsigned af[2][4], bf[4][4];
            ldsm4(af[0], acur + ((wm * 32 + arow) * GSP + kk + acolh) * 2);
            ldsm4(af[1], acur + ((wm * 32 + 16 + arow) * GSP + kk + acolh) * 2);
            #pragma unroll
            for (int p = 0; p < 4; p++)
                ldsm4(bf[p], bcur + ((wn * 64 + p * 16 + arow) * GSP + kk + acolh) * 2);
            #pragma unroll
            for (int mt = 0; mt < 2; mt++)
                #pragma unroll
                for (int p = 0; p < 4; p++) {
                    mma_fp16(acc[mt][p * 2],     af[mt], bf[p][0], bf[p][2]);
                    mma_fp16(acc[mt][p * 2 + 1], af[mt], bf[p][1], bf[p][3]);
                }
        }
    }

    #pragma unroll
    for (int mt = 0; mt < 2; mt++) {
        #pragma unroll
        for (int nt = 0; nt < 8; nt++) {
            float v0 = acc[mt][nt][0], v1 = acc[mt][nt][1];
            float v2 = acc[mt][nt][2], v3 = acc[mt][nt][3];
            if (SCALE) { v0 *= EXS; v1 *= EXS; v2 *= EXS; v3 *= EXS; }
            const int r0 = m0 + wm * 32 + mt * 16 + gid;
            const int cc = n0 + wn * 64 + nt * 8 + tig * 2;
            if (CH) {
                __half* C = (__half*)Cp;
                __half2 h0 = __floats2half2_rn(v0, v1);
                __half2 h1 = __floats2half2_rn(v2, v3);
                *(unsigned*)(C + (size_t)r0 * DD + cc)       = *(unsigned*)&h0;
                *(unsigned*)(C + (size_t)(r0 + 8) * DD + cc) = *(unsigned*)&h1;
            } else {
                float* C = (float*)Cp;
                *(float2*)(C + (size_t)r0 * DD + cc)       = make_float2(v0, v1);
                *(float2*)(C + (size_t)(r0 + 8) * DD + cc) = make_float2(v2, v3);
            }
        }
    }
}

// ---------------------------------------------------------------------------
// Fused bias + residual + LayerNorm (float4 vectorized; 256 thr x 4 elems).
// ---------------------------------------------------------------------------
__global__ __launch_bounds__(256) void ln_kernel(
    const float* __restrict__ po, const float* __restrict__ x,
    const float* __restrict__ bo, const float* __restrict__ gamma,
    const float* __restrict__ beta, float* __restrict__ y)
{
    const size_t row = blockIdx.x;
    const int t = threadIdx.x;
    const int c = t * 4;

    const float4 p4 = *(const float4*)(po + row * DD + c);
    const float4 x4 = *(const float4*)(x  + row * DD + c);
    const float4 b4 = *(const float4*)(bo + c);

    float4 u;
    u.x = p4.x + b4.x + x4.x;
    u.y = p4.y + b4.y + x4.y;
    u.z = p4.z + b4.z + x4.z;
    u.w = p4.w + b4.w + x4.w;

    float s  = u.x + u.y + u.z + u.w;
    float s2 = u.x * u.x + u.y * u.y + u.z * u.z + u.w * u.w;

    __shared__ float r1[8], r2[8];
    #pragma unroll
    for (int o = 16; o; o >>= 1) {
        s  += __shfl_xor_sync(0xffffffffu, s, o);
        s2 += __shfl_xor_sync(0xffffffffu, s2, o);
    }
    if ((t & 31) == 0) { r1[t >> 5] = s; r2[t >> 5] = s2; }
    __syncthreads();
    s = r1[0]; s2 = r2[0];
    #pragma unroll
    for (int i = 1; i < 8; i++) { s += r1[i]; s2 += r2[i]; }

    const float mu = s * (1.0f / DD);
    const float var = s2 * (1.0f / DD) - mu * mu;
    const float inv = rsqrtf(var + 1e-5f);

    const float4 g4 = *(const float4*)(gamma + c);
    const float4 be4 = *(const float4*)(beta + c);
    float4 o4;
    o4.x = (u.x - mu) * inv * g4.x + be4.x;
    o4.y = (u.y - mu) * inv * g4.y + be4.y;
    o4.z = (u.z - mu) * inv * g4.z + be4.z;
    o4.w = (u.w - mu) * inv * g4.w + be4.w;
    *(float4*)(y + row * DD + c) = o4;
}

// ---------------------------------------------------------------------------
extern "C" void kernel_launch(void* const* d_in, const int* in_sizes, int n_in,
                              void* d_out, int out_size)
{
    const float* x     = (const float*)d_in[0];
    const float* Wq    = (const float*)d_in[1];
    const float* Wk    = (const float*)d_in[2];
    const float* Wv    = (const float*)d_in[3];
    const float* Wo    = (const float*)d_in[4];
    const float* bo    = (const float*)d_in[5];
    const float* gamma = (const float*)d_in[6];
    const float* beta  = (const float*)d_in[7];

    __half *xh, *wh, *q, *k, *v, *ctx;
    float *po, *attn_scratch;
    cudaGetSymbolAddress((void**)&xh,  g_xh);
    cudaGetSymbolAddress((void**)&wh,  g_wh);
    cudaGetSymbolAddress((void**)&q,   g_q);
    cudaGetSymbolAddress((void**)&k,   g_k);
    cudaGetSymbolAddress((void**)&v,   g_v);
    cudaGetSymbolAddress((void**)&ctx, g_ctx);
    cudaGetSymbolAddress((void**)&po,  g_po);
    cudaGetSymbolAddress((void**)&attn_scratch, g_attn);

    const size_t Y   = (size_t)BB * SS * DD;
    const size_t ATT = (size_t)BB * HH * SS * SS;
    const size_t W   = (size_t)DD * DD;

    float* yout = (float*)d_out;
    const bool want_attn = ((size_t)out_size >= Y + ATT);
    float* attn = want_attn ? (yout + Y) : attn_scratch;

    const dim3 blk(256);

    // one combined fp32 -> fp16 conversion launch
    const int n4tot = N4X + 4 * N4W;
    f2h_multi<<<(n4tot + 255) / 256, blk>>>((const float4*)x, (const float4*)Wq,
                                            (const float4*)Wk, (const float4*)Wv,
                                            (const float4*)Wo, (uint2*)xh, (uint2*)wh);

    // Q/K/V projections (Q pre-scaled by EXS)
    cudaFuncSetAttribute(gemm_h<true, true>,   cudaFuncAttributeMaxDynamicSharedMemorySize, GEMM_SMEM_BYTES);
    cudaFuncSetAttribute(gemm_h<true, false>,  cudaFuncAttributeMaxDynamicSharedMemorySize, GEMM_SMEM_BYTES);
    cudaFuncSetAttribute(gemm_h<false, false>, cudaFuncAttributeMaxDynamicSharedMemorySize, GEMM_SMEM_BYTES);
    const dim3 gproj(DD / 128, (BB * SS) / 128, 1);
    gemm_h<true, true><<<gproj, blk, GEMM_SMEM_BYTES>>>(xh, wh + 0 * W, q);
    gemm_h<true, false><<<gproj, blk, GEMM_SMEM_BYTES>>>(xh, wh + 1 * W, k);
    gemm_h<true, false><<<gproj, blk, GEMM_SMEM_BYTES>>>(xh, wh + 2 * W, v);

    // fused attention
    const dim3 gatt(SS / 64, BB * HH);
    if (want_attn) {
        cudaFuncSetAttribute(attn_kernel<true>, cudaFuncAttributeMaxDynamicSharedMemorySize, SM_BYTES);
        attn_kernel<true><<<gatt, 256, SM_BYTES>>>(q, k, v, attn, ctx);
    } else {
        cudaFuncSetAttribute(attn_kernel<false>, cudaFuncAttributeMaxDynamicSharedMemorySize, SM_BYTES);
        attn_kernel<false><<<gatt, 256, SM_BYTES>>>(q, k, v, attn, ctx);
    }

    // output projection (fp16 in, fp32 out)
    gemm_h<false, false><<<gproj, blk, GEMM_SMEM_BYTES>>>(ctx, wh + 3 * W, po);

    // bias + residual + LayerNorm -> y
    ln_kernel<<<BB * SS, blk>>>(po, x, bo, gamma, beta, yout);
}

// round 12
// speedup vs baseline: 1.5583x; 1.5583x over previous
#include <cuda_runtime.h>
#include <cuda_fp16.h>

#define BB 2
#define SS 2048
#define DD 1024
#define HH 16
#define DK 64

// Scratch (allocation-free: __device__ globals)
__device__ __half g_xh[(size_t)BB * SS * DD];
__device__ __half g_wh[4 * (size_t)DD * DD];   // Wq,Wk,Wv,Wo fp16
__device__ __half g_q[(size_t)BB * SS * DD];   // pre-scaled by 0.125*log2(e)
__device__ __half g_k[(size_t)BB * SS * DD];
__device__ __half g_v[(size_t)BB * SS * DD];
__device__ __half g_ctx[(size_t)BB * SS * DD];
__device__ float  g_po[(size_t)BB * SS * DD];
__device__ float  g_attn[(size_t)BB * HH * SS * SS];

#define EXS 0.18033688011112043f  /* 0.125 * log2(e) */

__device__ __forceinline__ float ex2f(float x) {
    float y;
    asm("ex2.approx.ftz.f32 %0, %1;" : "=f"(y) : "f"(x));
    return y;
}

__device__ __forceinline__ void mma_fp16(float* c, const unsigned* a, unsigned b0, unsigned b1) {
    asm volatile(
        "mma.sync.aligned.m16n8k16.row.col.f32.f16.f16.f32 "
        "{%0,%1,%2,%3}, {%4,%5,%6,%7}, {%8,%9}, {%0,%1,%2,%3};\n"
        : "+f"(c[0]), "+f"(c[1]), "+f"(c[2]), "+f"(c[3])
        : "r"(a[0]), "r"(a[1]), "r"(a[2]), "r"(a[3]), "r"(b0), "r"(b1));
}

__device__ __forceinline__ void ldsm4(unsigned* r, unsigned addr) {
    asm volatile("ldmatrix.sync.aligned.m8n8.x4.shared.b16 {%0,%1,%2,%3}, [%4];"
                 : "=r"(r[0]), "=r"(r[1]), "=r"(r[2]), "=r"(r[3]) : "r"(addr));
}

__device__ __forceinline__ void ldsm4t(unsigned* r, unsigned addr) {
    asm volatile("ldmatrix.sync.aligned.m8n8.x4.trans.shared.b16 {%0,%1,%2,%3}, [%4];"
                 : "=r"(r[0]), "=r"(r[1]), "=r"(r[2]), "=r"(r[3]) : "r"(addr));
}

#define CP_A16(dst, src) asm volatile("cp.async.cg.shared.global [%0], [%1], 16;\n" :: "r"(dst), "l"(src))
#define CP_COMMIT()      asm volatile("cp.async.commit_group;\n")
#define CP_WAIT1()       asm volatile("cp.async.wait_group 1;\n")
#define CP_WAIT0()       asm volatile("cp.async.wait_group 0;\n")

// ---------------------------------------------------------------------------
// Combined fp32 -> fp16 converter: x then the 4 weight matrices, one launch.
// ---------------------------------------------------------------------------
#define N4X ((int)((size_t)BB * SS * DD / 4))
#define N4W ((int)((size_t)DD * DD / 4))

__global__ __launch_bounds__(256) void f2h_multi(
    const float4* __restrict__ x,  const float4* __restrict__ wq,
    const float4* __restrict__ wk, const float4* __restrict__ wv,
    const float4* __restrict__ wo, uint2* __restrict__ xh, uint2* __restrict__ wh)
{
    const int i = blockIdx.x * 256 + threadIdx.x;
    const float4* src;
    uint2* dst;
    int off;
    if (i < N4X) {
        src = x; dst = xh; off = i;
    } else {
        const int j = i - N4X;
        const int seg = j / N4W;
        off = j - seg * N4W;
        src = (seg == 0) ? wq : (seg == 1) ? wk : (seg == 2) ? wv : wo;
        dst = wh + (size_t)seg * N4W;
    }
    const float4 v = src[off];
    __half2 h0 = __floats2half2_rn(v.x, v.y);
    __half2 h1 = __floats2half2_rn(v.z, v.w);
    dst[off] = make_uint2(*(unsigned*)&h0, *(unsigned*)&h1);
}

// ===========================================================================
// Attention kernel (R10 pipeline structure). Q pre-scaled so p = exp2(QK).
// 64 q rows / CTA, 256 threads (8 warps 2x4), 2 CTAs/SM, cp.async pipelined.
// ===========================================================================
#define QSP 72
#define KSP 72
#define VSP 72
#define PSP 136

#define SM_QS 0
#define SM_K0 4608
#define KTILE 9216
#define SM_V0 (SM_K0 + 2 * KTILE)
#define SM_PS (SM_V0 + 2 * KTILE)
#define SM_ENDH (SM_PS + 64 * PSP)
#define SM_BYTES (SM_ENDH * 2 + 64 * 4)

template <bool WRITE_ATTN>
__global__ __launch_bounds__(256, 2) void attn_kernel(
    const __half* __restrict__ q, const __half* __restrict__ k,
    const __half* __restrict__ v, float* __restrict__ attn,
    __half* __restrict__ ctx)
{
    extern __shared__ __half smh[];
    __half* Ps = smh + SM_PS;
    float* rs  = (float*)(smh + SM_ENDH);

    const unsigned smu = (unsigned)__cvta_generic_to_shared(smh);
    const unsigned QsU = smu + SM_QS * 2;
    const unsigned KsU = smu + SM_K0 * 2;
    const unsigned VsU = smu + SM_V0 * 2;
    const unsigned PsU = smu + SM_PS * 2;

    const int z = blockIdx.y;
    const int b = z >> 4, h = z & 15;
    const size_t base = (size_t)b * SS * DD + (size_t)h * DK;
    const int q0 = blockIdx.x * 64;

    const __half* qp = q + base + (size_t)q0 * DD;
    const __half* kp = k + base;
    const __half* vp = v + base;
    float* attp = attn + (size_t)z * SS * SS + (size_t)q0 * SS;

    const int tid = threadIdx.x;
    const int warp = tid >> 5, l = tid & 31;
    const int gid = l >> 2, tig = l & 3;
    const int wm = warp >> 2, wn = warp & 3;

    const int arow  = (l & 7) + ((l >> 3) & 1) * 8;
    const int acolh = (l >> 4) * 8;

    const int crow0 = tid >> 3, cch = (tid & 7) * 8;

    #pragma unroll
    for (int i = 0; i < 2; i++) {
        const int row = crow0 + i * 32;
        CP_A16(QsU + (row * QSP + cch) * 2, qp + (size_t)row * DD + cch);
    }
    #pragma unroll
    for (int i = 0; i < 4; i++) {
        const int row = crow0 + i * 32;
        CP_A16(KsU + (row * KSP + cch) * 2, kp + (size_t)row * DD + cch);
    }
    CP_COMMIT();
    if (tid < 64) rs[tid] = 0.f;

    float rsum[2][2] = {};

    // =================== PASS 1: row sums ===================
    for (int kt = 0; kt < SS / 128; kt++) {
        if (kt < 15) {
            const unsigned kb = KsU + ((kt + 1) & 1) * KTILE * 2;
            #pragma unroll
            for (int i = 0; i < 4; i++) {
                const int row = crow0 + i * 32;
                CP_A16(kb + (row * KSP + cch) * 2, kp + (size_t)((kt + 1) * 128 + row) * DD + cch);
            }
            CP_COMMIT();
            CP_WAIT1();
        } else {
            CP_WAIT0();
        }
        __syncthreads();

        const unsigned kcur = KsU + (kt & 1) * KTILE * 2;
        float c[2][4][4] = {};
        #pragma unroll
        for (int kk = 0; kk < DK; kk += 16) {
            unsigned af[2][4], bf[2][4];
            ldsm4(af[0], QsU + ((wm * 32 + arow) * QSP + kk + acolh) * 2);
            ldsm4(af[1], QsU + ((wm * 32 + 16 + arow) * QSP + kk + acolh) * 2);
            ldsm4(bf[0], kcur + ((wn * 32 + arow) * KSP + kk + acolh) * 2);
            ldsm4(bf[1], kcur + ((wn * 32 + 16 + arow) * KSP + kk + acolh) * 2);
            #pragma unroll
            for (int mt = 0; mt < 2; mt++) {
                mma_fp16(c[mt][0], af[mt], bf[0][0], bf[0][2]);
                mma_fp16(c[mt][1], af[mt], bf[0][1], bf[0][3]);
                mma_fp16(c[mt][2], af[mt], bf[1][0], bf[1][2]);
                mma_fp16(c[mt][3], af[mt], bf[1][1], bf[1][3]);
            }
        }
        #pragma unroll
        for (int mt = 0; mt < 2; mt++)
            #pragma unroll
            for (int nt = 0; nt < 4; nt++) {
                rsum[mt][0] += ex2f(c[mt][nt][0]) + ex2f(c[mt][nt][1]);
                rsum[mt][1] += ex2f(c[mt][nt][2]) + ex2f(c[mt][nt][3]);
            }
        __syncthreads();
    }

    #pragma unroll
    for (int mt = 0; mt < 2; mt++)
        #pragma unroll
        for (int hf = 0; hf < 2; hf++) {
            float v0 = rsum[mt][hf];
            v0 += __shfl_xor_sync(0xffffffffu, v0, 1);
            v0 += __shfl_xor_sync(0xffffffffu, v0, 2);
            if (tig == 0) atomicAdd(&rs[wm * 32 + mt * 16 + hf * 8 + gid], v0);
        }
    __syncthreads();

    float inv[2][2];
    #pragma unroll
    for (int mt = 0; mt < 2; mt++)
        #pragma unroll
        for (int hf = 0; hf < 2; hf++)
            inv[mt][hf] = 1.0f / rs[wm * 32 + mt * 16 + hf * 8 + gid];

    float cacc[2][2][4] = {};

    #pragma unroll
    for (int i = 0; i < 4; i++) {
        const int row = crow0 + i * 32;
        CP_A16(KsU + (row * KSP + cch) * 2, kp + (size_t)row * DD + cch);
        CP_A16(VsU + (row * VSP + cch) * 2, vp + (size_t)row * DD + cch);
    }
    CP_COMMIT();

    // =================== PASS 2 ===================
    for (int kt = 0; kt < SS / 128; kt++) {
        if (kt < 15) {
            const unsigned kb = KsU + ((kt + 1) & 1) * KTILE * 2;
            const unsigned vb = VsU + ((kt + 1) & 1) * KTILE * 2;
            #pragma unroll
            for (int i = 0; i < 4; i++) {
                const int row = crow0 + i * 32;
                CP_A16(kb + (row * KSP + cch) * 2, kp + (size_t)((kt + 1) * 128 + row) * DD + cch);
                CP_A16(vb + (row * VSP + cch) * 2, vp + (size_t)((kt + 1) * 128 + row) * DD + cch);
            }
            CP_COMMIT();
            CP_WAIT1();
        } else {
            CP_WAIT0();
        }
        __syncthreads();

        const unsigned kcur = KsU + (kt & 1) * KTILE * 2;
        const unsigned vcur = VsU + (kt & 1) * KTILE * 2;

        float c[2][4][4] = {};
        #pragma unroll
        for (int kk = 0; kk < DK; kk += 16) {
            unsigned af[2][4], bf[2][4];
            ldsm4(af[0], QsU + ((wm * 32 + arow) * QSP + kk + acolh) * 2);
            ldsm4(af[1], QsU + ((wm * 32 + 16 + arow) * QSP + kk + acolh) * 2);
            ldsm4(bf[0], kcur + ((wn * 32 + arow) * KSP + kk + acolh) * 2);
            ldsm4(bf[1], kcur + ((wn * 32 + 16 + arow) * KSP + kk + acolh) * 2);
            #pragma unroll
            for (int mt = 0; mt < 2; mt++) {
                mma_fp16(c[mt][0], af[mt], bf[0][0], bf[0][2]);
                mma_fp16(c[mt][1], af[mt], bf[0][1], bf[0][3]);
                mma_fp16(c[mt][2], af[mt], bf[1][0], bf[1][2]);
                mma_fp16(c[mt][3], af[mt], bf[1][1], bf[1][3]);
            }
        }

        #pragma unroll
        for (int mt = 0; mt < 2; mt++) {
            const int r0 = wm * 32 + mt * 16 + gid;
            #pragma unroll
            for (int nt = 0; nt < 4; nt++) {
                const int cl = wn * 32 + nt * 8 + 2 * tig;
                __half2 h0 = __floats2half2_rn(ex2f(c[mt][nt][0]) * inv[mt][0],
                                               ex2f(c[mt][nt][1]) * inv[mt][0]);
                __half2 h1 = __floats2half2_rn(ex2f(c[mt][nt][2]) * inv[mt][1],
                                               ex2f(c[mt][nt][3]) * inv[mt][1]);
                *(unsigned*)&Ps[r0 * PSP + cl]       = *(unsigned*)&h0;
                *(unsigned*)&Ps[(r0 + 8) * PSP + cl] = *(unsigned*)&h1;
            }
        }
        __syncthreads();

        #pragma unroll
        for (int kk = 0; kk < 128; kk += 16) {
            unsigned af[2][4], bf[4];
            ldsm4(af[0], PsU + ((wm * 32 + arow) * PSP + kk + acolh) * 2);
            ldsm4(af[1], PsU + ((wm * 32 + 16 + arow) * PSP + kk + acolh) * 2);
            ldsm4t(bf, vcur + ((kk + arow) * VSP + wn * 16 + acolh) * 2);
            #pragma unroll
            for (int mt = 0; mt < 2; mt++) {
                mma_fp16(cacc[mt][0], af[mt], bf[0], bf[1]);
                mma_fp16(cacc[mt][1], af[mt], bf[2], bf[3]);
            }
        }

        if (WRITE_ATTN) {
            #pragma unroll
            for (int i = 0; i < 8; i++) {
                const int idx = tid + i * 256;
                const int row = idx >> 5, c4 = idx & 31;
                const uint2 hraw = *(const uint2*)&Ps[row * PSP + c4 * 4];
                const float2 f01 = __half22float2(*(const __half2*)&hraw.x);
                const float2 f23 = __half22float2(*(const __half2*)&hraw.y);
                *(float4*)(attp + (size_t)row * SS + kt * 128 + c4 * 4) =
                    make_float4(f01.x, f01.y, f23.x, f23.y);
            }
        }
        __syncthreads();
    }

    __half* cp = ctx + base + (size_t)q0 * DD;
    #pragma unroll
    for (int mt = 0; mt < 2; mt++) {
        const int r0 = wm * 32 + mt * 16 + gid;
        #pragma unroll
        for (int nt = 0; nt < 2; nt++) {
            const int cl = wn * 16 + nt * 8 + 2 * tig;
            __half2 h0 = __floats2half2_rn(cacc[mt][nt][0], cacc[mt][nt][1]);
            __half2 h1 = __floats2half2_rn(cacc[mt][nt][2], cacc[mt][nt][3]);
            *(unsigned*)(cp + (size_t)r0 * DD + cl)       = *(unsigned*)&h0;
            *(unsigned*)(cp + (size_t)(r0 + 8) * DD + cl) = *(unsigned*)&h1;
        }
    }
}

// ===========================================================================
// Projection GEMM (R10 pipeline structure), all-fp16, cp.async double-buffered.
// C = A @ B^T, 128x128x64 tile, 256 threads (8 warps 4x2), 2 CTAs/SM.
// SCALE: multiply output by EXS (Q projection).
// ===========================================================================
#define GSP 72
#define GTILE (128 * GSP)
#define GEMM_SMEM_BYTES (4 * GTILE * 2)

template <bool CH, bool SCALE>
__global__ __launch_bounds__(256, 2) void gemm_h(
    const __half* __restrict__ A, const __half* __restrict__ Bm, void* __restrict__ Cp)
{
    extern __shared__ __half gsm[];
    const unsigned smu = (unsigned)__cvta_generic_to_shared(gsm);
    const unsigned AsU = smu;
    const unsigned BsU = smu + 2 * GTILE * 2;

    const int tid = threadIdx.x;
    const int warp = tid >> 5, l = tid & 31;
    const int gid = l >> 2, tig = l & 3;
    const int wm = warp >> 1, wn = warp & 1;
    const int m0 = blockIdx.y * 128;
    const int n0 = blockIdx.x * 128;

    const int arow  = (l & 7) + ((l >> 3) & 1) * 8;
    const int acolh = (l >> 4) * 8;

    const int crow0 = tid >> 3, cch = (tid & 7) * 8;

    float acc[2][8][4] = {};

    #pragma unroll
    for (int i = 0; i < 4; i++) {
        const int row = crow0 + i * 32;
        CP_A16(AsU + (row * GSP + cch) * 2, A  + (size_t)(m0 + row) * DD + cch);
        CP_A16(BsU + (row * GSP + cch) * 2, Bm + (size_t)(n0 + row) * DD + cch);
    }
    CP_COMMIT();

    for (int it = 0; it < DD / 64; it++) {
        if (it < DD / 64 - 1) {
            const unsigned ab = AsU + ((it + 1) & 1) * GTILE * 2;
            const unsigned bb = BsU + ((it + 1) & 1) * GTILE * 2;
            const int k0 = (it + 1) * 64;
            #pragma unroll
            for (int i = 0; i < 4; i++) {
                const int row = crow0 + i * 32;
                CP_A16(ab + (row * GSP + cch) * 2, A  + (size_t)(m0 + row) * DD + k0 + cch);
                CP_A16(bb + (row * GSP + cch) * 2, Bm + (size_t)(n0 + row) * DD + k0 + cch);
            }
            CP_COMMIT();
            CP_WAIT1();
        } else {
            CP_WAIT0();
        }
        __syncthreads();

        const unsigned acur = AsU + (it & 1) * GTILE * 2;
        const unsigned bcur = BsU + (it & 1) * GTILE * 2;

        #pragma unroll
        for (int kk = 0; kk < 64; kk += 16) {
            unsigned af[2][4], bf[4][4];
            ldsm4(af[0], acur + ((wm * 32 + arow) * GSP + kk + acolh) * 2);
            ldsm4(af[1], acur + ((wm * 32 + 16 + arow) * GSP + kk + acolh) * 2);
            #pragma unroll
            for (int p = 0; p < 4; p++)
                ldsm4(bf[p], bcur + ((wn * 64 + p * 16 + arow) * GSP + kk + acolh) * 2);
            #pragma unroll
            for (int mt = 0; mt < 2; mt++)
                #pragma unroll
                for (int p = 0; p < 4; p++) {
                    mma_fp16(acc[mt][p * 2],     af[mt], bf[p][0], bf[p][2]);
                    mma_fp16(acc[mt][p * 2 + 1], af[mt], bf[p][1], bf[p][3]);
                }
        }
        __syncthreads();
    }

    #pragma unroll
    for (int mt = 0; mt < 2; mt++) {
        #pragma unroll
        for (int nt = 0; nt < 8; nt++) {
            float v0 = acc[mt][nt][0], v1 = acc[mt][nt][1];
            float v2 = acc[mt][nt][2], v3 = acc[mt][nt][3];
            if (SCALE) { v0 *= EXS; v1 *= EXS; v2 *= EXS; v3 *= EXS; }
            const int r0 = m0 + wm * 32 + mt * 16 + gid;
            const int cc = n0 + wn * 64 + nt * 8 + tig * 2;
            if (CH) {
                __half* C = (__half*)Cp;
                __half2 h0 = __floats2half2_rn(v0, v1);
                __half2 h1 = __floats2half2_rn(v2, v3);
                *(unsigned*)(C + (size_t)r0 * DD + cc)       = *(unsigned*)&h0;
                *(unsigned*)(C + (size_t)(r0 + 8) * DD + cc) = *(unsigned*)&h1;
            } else {
                float* C = (float*)Cp;
                *(float2*)(C + (size_t)r0 * DD + cc)       = make_float2(v0, v1);
                *(float2*)(C + (size_t)(r0 + 8) * DD + cc) = make_float2(v2, v3);
            }
        }
    }
}

// ---------------------------------------------------------------------------
// Fused bias + residual + LayerNorm (float4 vectorized).
// ---------------------------------------------------------------------------
__global__ __launch_bounds__(256) void ln_kernel(
    const float* __restrict__ po, const float* __restrict__ x,
    const float* __restrict__ bo, const float* __restrict__ gamma,
    const float* __restrict__ beta, float* __restrict__ y)
{
    const size_t row = blockIdx.x;
    const int t = threadIdx.x;
    const int c = t * 4;

    const float4 p4 = *(const float4*)(po + row * DD + c);
    const float4 x4 = *(const float4*)(x  + row * DD + c);
    const float4 b4 = *(const float4*)(bo + c);

    float4 u;
    u.x = p4.x + b4.x + x4.x;
    u.y = p4.y + b4.y + x4.y;
    u.z = p4.z + b4.z + x4.z;
    u.w = p4.w + b4.w + x4.w;

    float s  = u.x + u.y + u.z + u.w;
    float s2 = u.x * u.x + u.y * u.y + u.z * u.z + u.w * u.w;

    __shared__ float r1[8], r2[8];
    #pragma unroll
    for (int o = 16; o; o >>= 1) {
        s  += __shfl_xor_sync(0xffffffffu, s, o);
        s2 += __shfl_xor_sync(0xffffffffu, s2, o);
    }
    if ((t & 31) == 0) { r1[t >> 5] = s; r2[t >> 5] = s2; }
    __syncthreads();
    s = r1[0]; s2 = r2[0];
    #pragma unroll
    for (int i = 1; i < 8; i++) { s += r1[i]; s2 += r2[i]; }

    const float mu = s * (1.0f / DD);
    const float var = s2 * (1.0f / DD) - mu * mu;
    const float inv = rsqrtf(var + 1e-5f);

    const float4 g4 = *(const float4*)(gamma + c);
    const float4 be4 = *(const float4*)(beta + c);
    float4 o4;
    o4.x = (u.x - mu) * inv * g4.x + be4.x;
    o4.y = (u.y - mu) * inv * g4.y + be4.y;
    o4.z = (u.z - mu) * inv * g4.z + be4.z;
    o4.w = (u.w - mu) * inv * g4.w + be4.w;
    *(float4*)(y + row * DD + c) = o4;
}

// ---------------------------------------------------------------------------
extern "C" void kernel_launch(void* const* d_in, const int* in_sizes, int n_in,
                              void* d_out, int out_size)
{
    const float* x     = (const float*)d_in[0];
    const float* Wq    = (const float*)d_in[1];
    const float* Wk    = (const float*)d_in[2];
    const float* Wv    = (const float*)d_in[3];
    const float* Wo    = (const float*)d_in[4];
    const float* bo    = (const float*)d_in[5];
    const float* gamma = (const float*)d_in[6];
    const float* beta  = (const float*)d_in[7];

    __half *xh, *wh, *q, *k, *v, *ctx;
    float *po, *attn_scratch;
    cudaGetSymbolAddress((void**)&xh,  g_xh);
    cudaGetSymbolAddress((void**)&wh,  g_wh);
    cudaGetSymbolAddress((void**)&q,   g_q);
    cudaGetSymbolAddress((void**)&k,   g_k);
    cudaGetSymbolAddress((void**)&v,   g_v);
    cudaGetSymbolAddress((void**)&ctx, g_ctx);
    cudaGetSymbolAddress((void**)&po,  g_po);
    cudaGetSymbolAddress((void**)&attn_scratch, g_attn);

    const size_t Y   = (size_t)BB * SS * DD;
    const size_t ATT = (size_t)BB * HH * SS * SS;
    const size_t W   = (size_t)DD * DD;

    float* yout = (float*)d_out;
    const bool want_attn = ((size_t)out_size >= Y + ATT);
    float* attn = want_attn ? (yout + Y) : attn_scratch;

    const dim3 blk(256);

    // one combined fp32 -> fp16 conversion launch
    const int n4tot = N4X + 4 * N4W;
    f2h_multi<<<(n4tot + 255) / 256, blk>>>((const float4*)x, (const float4*)Wq,
                                            (const float4*)Wk, (const float4*)Wv,
                                            (const float4*)Wo, (uint2*)xh, (uint2*)wh);

    // Q/K/V projections (Q pre-scaled by EXS)
    cudaFuncSetAttribute(gemm_h<true, true>,   cudaFuncAttributeMaxDynamicSharedMemorySize, GEMM_SMEM_BYTES);
    cudaFuncSetAttribute(gemm_h<true, false>,  cudaFuncAttributeMaxDynamicSharedMemorySize, GEMM_SMEM_BYTES);
    cudaFuncSetAttribute(gemm_h<false, false>, cudaFuncAttributeMaxDynamicSharedMemorySize, GEMM_SMEM_BYTES);
    const dim3 gproj(DD / 128, (BB * SS) / 128, 1);
    gemm_h<true, true><<<gproj, blk, GEMM_SMEM_BYTES>>>(xh, wh + 0 * W, q);
    gemm_h<true, false><<<gproj, blk, GEMM_SMEM_BYTES>>>(xh, wh + 1 * W, k);
    gemm_h<true, false><<<gproj, blk, GEMM_SMEM_BYTES>>>(xh, wh + 2 * W, v);

    // fused attention
    const dim3 gatt(SS / 64, BB * HH);
    if (want_attn) {
        cudaFuncSetAttribute(attn_kernel<true>, cudaFuncAttributeMaxDynamicSharedMemorySize, SM_BYTES);
        attn_kernel<true><<<gatt, 256, SM_BYTES>>>(q, k, v, attn, ctx);
    } else {
        cudaFuncSetAttribute(attn_kernel<false>, cudaFuncAttributeMaxDynamicSharedMemorySize, SM_BYTES);
        attn_kernel<false><<<gatt, 256, SM_BYTES>>>(q, k, v, attn, ctx);
    }

    // output projection (fp16 in, fp32 out)
    gemm_h<false, false><<<gproj, blk, GEMM_SMEM_BYTES>>>(ctx, wh + 3 * W, po);

    // bias + residual + LayerNorm -> y
    ln_kernel<<<BB * SS, blk>>>(po, x, bo, gamma, beta, yout);
}

// round 13
// speedup vs baseline: 1.5793x; 1.0135x over previous
#include <cuda_runtime.h>
#include <cuda_fp16.h>

#define BB 2
#define SS 2048
#define DD 1024
#define HH 16
#define DK 64

// Scratch (allocation-free: __device__ globals)
__device__ __half g_xh[(size_t)BB * SS * DD];
__device__ __half g_wh[4 * (size_t)DD * DD];   // Wq,Wk,Wv,Wo fp16 (contiguous)
__device__ __half g_q[(size_t)BB * SS * DD];   // pre-scaled by 0.125*log2(e)
__device__ __half g_k[(size_t)BB * SS * DD];
__device__ __half g_v[(size_t)BB * SS * DD];
__device__ __half g_ctx[(size_t)BB * SS * DD];
__device__ float  g_po[(size_t)BB * SS * DD];
__device__ float  g_attn[(size_t)BB * HH * SS * SS];

#define EXS 0.18033688011112043f  /* 0.125 * log2(e) */

__device__ __forceinline__ float ex2f(float x) {
    float y;
    asm("ex2.approx.ftz.f32 %0, %1;" : "=f"(y) : "f"(x));
    return y;
}

__device__ __forceinline__ void mma_fp16(float* c, const unsigned* a, unsigned b0, unsigned b1) {
    asm volatile(
        "mma.sync.aligned.m16n8k16.row.col.f32.f16.f16.f32 "
        "{%0,%1,%2,%3}, {%4,%5,%6,%7}, {%8,%9}, {%0,%1,%2,%3};\n"
        : "+f"(c[0]), "+f"(c[1]), "+f"(c[2]), "+f"(c[3])
        : "r"(a[0]), "r"(a[1]), "r"(a[2]), "r"(a[3]), "r"(b0), "r"(b1));
}

__device__ __forceinline__ void ldsm4(unsigned* r, unsigned addr) {
    asm volatile("ldmatrix.sync.aligned.m8n8.x4.shared.b16 {%0,%1,%2,%3}, [%4];"
                 : "=r"(r[0]), "=r"(r[1]), "=r"(r[2]), "=r"(r[3]) : "r"(addr));
}

__device__ __forceinline__ void ldsm4t(unsigned* r, unsigned addr) {
    asm volatile("ldmatrix.sync.aligned.m8n8.x4.trans.shared.b16 {%0,%1,%2,%3}, [%4];"
                 : "=r"(r[0]), "=r"(r[1]), "=r"(r[2]), "=r"(r[3]) : "r"(addr));
}

#define CP_A16(dst, src) asm volatile("cp.async.cg.shared.global [%0], [%1], 16;\n" :: "r"(dst), "l"(src))
#define CP_COMMIT()      asm volatile("cp.async.commit_group;\n")
#define CP_WAIT1()       asm volatile("cp.async.wait_group 1;\n")
#define CP_WAIT0()       asm volatile("cp.async.wait_group 0;\n")

// ---------------------------------------------------------------------------
// Combined fp32 -> fp16 converter: x then the 4 weight matrices, one launch.
// ---------------------------------------------------------------------------
#define N4X ((int)((size_t)BB * SS * DD / 4))
#define N4W ((int)((size_t)DD * DD / 4))

__global__ __launch_bounds__(256) void f2h_multi(
    const float4* __restrict__ x,  const float4* __restrict__ wq,
    const float4* __restrict__ wk, const float4* __restrict__ wv,
    const float4* __restrict__ wo, uint2* __restrict__ xh, uint2* __restrict__ wh)
{
    const int i = blockIdx.x * 256 + threadIdx.x;
    const float4* src;
    uint2* dst;
    int off;
    if (i < N4X) {
        src = x; dst = xh; off = i;
    } else {
        const int j = i - N4X;
        const int seg = j / N4W;
        off = j - seg * N4W;
        src = (seg == 0) ? wq : (seg == 1) ? wk : (seg == 2) ? wv : wo;
        dst = wh + (size_t)seg * N4W;
    }
    const float4 v = src[off];
    __half2 h0 = __floats2half2_rn(v.x, v.y);
    __half2 h1 = __floats2half2_rn(v.z, v.w);
    dst[off] = make_uint2(*(unsigned*)&h0, *(unsigned*)&h1);
}

// ===========================================================================
// Attention kernel (R10/R12 pipeline). Q pre-scaled so p = exp2(QK).
// 64 q rows / CTA, 256 threads (8 warps 2x4), 2 CTAs/SM, cp.async pipelined.
// ===========================================================================
#define QSP 72
#define KSP 72
#define VSP 72
#define PSP 136

#define SM_QS 0
#define SM_K0 4608
#define KTILE 9216
#define SM_V0 (SM_K0 + 2 * KTILE)
#define SM_PS (SM_V0 + 2 * KTILE)
#define SM_ENDH (SM_PS + 64 * PSP)
#define SM_BYTES (SM_ENDH * 2 + 64 * 4)

template <bool WRITE_ATTN>
__global__ __launch_bounds__(256, 2) void attn_kernel(
    const __half* __restrict__ q, const __half* __restrict__ k,
    const __half* __restrict__ v, float* __restrict__ attn,
    __half* __restrict__ ctx)
{
    extern __shared__ __half smh[];
    __half* Ps = smh + SM_PS;
    float* rs  = (float*)(smh + SM_ENDH);

    const unsigned smu = (unsigned)__cvta_generic_to_shared(smh);
    const unsigned QsU = smu + SM_QS * 2;
    const unsigned KsU = smu + SM_K0 * 2;
    const unsigned VsU = smu + SM_V0 * 2;
    const unsigned PsU = smu + SM_PS * 2;

    const int z = blockIdx.y;
    const int b = z >> 4, h = z & 15;
    const size_t base = (size_t)b * SS * DD + (size_t)h * DK;
    const int q0 = blockIdx.x * 64;

    const __half* qp = q + base + (size_t)q0 * DD;
    const __half* kp = k + base;
    const __half* vp = v + base;
    float* attp = attn + (size_t)z * SS * SS + (size_t)q0 * SS;

    const int tid = threadIdx.x;
    const int warp = tid >> 5, l = tid & 31;
    const int gid = l >> 2, tig = l & 3;
    const int wm = warp >> 2, wn = warp & 3;

    const int arow  = (l & 7) + ((l >> 3) & 1) * 8;
    const int acolh = (l >> 4) * 8;

    const int crow0 = tid >> 3, cch = (tid & 7) * 8;

    #pragma unroll
    for (int i = 0; i < 2; i++) {
        const int row = crow0 + i * 32;
        CP_A16(QsU + (row * QSP + cch) * 2, qp + (size_t)row * DD + cch);
    }
    #pragma unroll
    for (int i = 0; i < 4; i++) {
        const int row = crow0 + i * 32;
        CP_A16(KsU + (row * KSP + cch) * 2, kp + (size_t)row * DD + cch);
    }
    CP_COMMIT();
    if (tid < 64) rs[tid] = 0.f;

    float rsum[2][2] = {};

    // =================== PASS 1: row sums ===================
    for (int kt = 0; kt < SS / 128; kt++) {
        if (kt < 15) {
            const unsigned kb = KsU + ((kt + 1) & 1) * KTILE * 2;
            #pragma unroll
            for (int i = 0; i < 4; i++) {
                const int row = crow0 + i * 32;
                CP_A16(kb + (row * KSP + cch) * 2, kp + (size_t)((kt + 1) * 128 + row) * DD + cch);
            }
            CP_COMMIT();
            CP_WAIT1();
        } else {
            CP_WAIT0();
        }
        __syncthreads();

        const unsigned kcur = KsU + (kt & 1) * KTILE * 2;
        float c[2][4][4] = {};
        #pragma unroll
        for (int kk = 0; kk < DK; kk += 16) {
            unsigned af[2][4], bf[2][4];
            ldsm4(af[0], QsU + ((wm * 32 + arow) * QSP + kk + acolh) * 2);
            ldsm4(af[1], QsU + ((wm * 32 + 16 + arow) * QSP + kk + acolh) * 2);
            ldsm4(bf[0], kcur + ((wn * 32 + arow) * KSP + kk + acolh) * 2);
            ldsm4(bf[1], kcur + ((wn * 32 + 16 + arow) * KSP + kk + acolh) * 2);
            #pragma unroll
            for (int mt = 0; mt < 2; mt++) {
                mma_fp16(c[mt][0], af[mt], bf[0][0], bf[0][2]);
                mma_fp16(c[mt][1], af[mt], bf[0][1], bf[0][3]);
                mma_fp16(c[mt][2], af[mt], bf[1][0], bf[1][2]);
                mma_fp16(c[mt][3], af[mt], bf[1][1], bf[1][3]);
            }
        }
        #pragma unroll
        for (int mt = 0; mt < 2; mt++)
            #pragma unroll
            for (int nt = 0; nt < 4; nt++) {
                rsum[mt][0] += ex2f(c[mt][nt][0]) + ex2f(c[mt][nt][1]);
                rsum[mt][1] += ex2f(c[mt][nt][2]) + ex2f(c[mt][nt][3]);
            }
        __syncthreads();
    }

    #pragma unroll
    for (int mt = 0; mt < 2; mt++)
        #pragma unroll
        for (int hf = 0; hf < 2; hf++) {
            float v0 = rsum[mt][hf];
            v0 += __shfl_xor_sync(0xffffffffu, v0, 1);
            v0 += __shfl_xor_sync(0xffffffffu, v0, 2);
            if (tig == 0) atomicAdd(&rs[wm * 32 + mt * 16 + hf * 8 + gid], v0);
        }
    __syncthreads();

    float inv[2][2];
    #pragma unroll
    for (int mt = 0; mt < 2; mt++)
        #pragma unroll
        for (int hf = 0; hf < 2; hf++)
            inv[mt][hf] = 1.0f / rs[wm * 32 + mt * 16 + hf * 8 + gid];

    float cacc[2][2][4] = {};

    #pragma unroll
    for (int i = 0; i < 4; i++) {
        const int row = crow0 + i * 32;
        CP_A16(KsU + (row * KSP + cch) * 2, kp + (size_t)row * DD + cch);
        CP_A16(VsU + (row * VSP + cch) * 2, vp + (size_t)row * DD + cch);
    }
    CP_COMMIT();

    // =================== PASS 2 ===================
    for (int kt = 0; kt < SS / 128; kt++) {
        if (kt < 15) {
            const unsigned kb = KsU + ((kt + 1) & 1) * KTILE * 2;
            const unsigned vb = VsU + ((kt + 1) & 1) * KTILE * 2;
            #pragma unroll
            for (int i = 0; i < 4; i++) {
                const int row = crow0 + i * 32;
                CP_A16(kb + (row * KSP + cch) * 2, kp + (size_t)((kt + 1) * 128 + row) * DD + cch);
                CP_A16(vb + (row * VSP + cch) * 2, vp + (size_t)((kt + 1) * 128 + row) * DD + cch);
            }
            CP_COMMIT();
            CP_WAIT1();
        } else {
            CP_WAIT0();
        }
        __syncthreads();

        const unsigned kcur = KsU + (kt & 1) * KTILE * 2;
        const unsigned vcur = VsU + (kt & 1) * KTILE * 2;

        float c[2][4][4] = {};
        #pragma unroll
        for (int kk = 0; kk < DK; kk += 16) {
            unsigned af[2][4], bf[2][4];
            ldsm4(af[0], QsU + ((wm * 32 + arow) * QSP + kk + acolh) * 2);
            ldsm4(af[1], QsU + ((wm * 32 + 16 + arow) * QSP + kk + acolh) * 2);
            ldsm4(bf[0], kcur + ((wn * 32 + arow) * KSP + kk + acolh) * 2);
            ldsm4(bf[1], kcur + ((wn * 32 + 16 + arow) * KSP + kk + acolh) * 2);
            #pragma unroll
            for (int mt = 0; mt < 2; mt++) {
                mma_fp16(c[mt][0], af[mt], bf[0][0], bf[0][2]);
                mma_fp16(c[mt][1], af[mt], bf[0][1], bf[0][3]);
                mma_fp16(c[mt][2], af[mt], bf[1][0], bf[1][2]);
                mma_fp16(c[mt][3], af[mt], bf[1][1], bf[1][3]);
            }
        }

        #pragma unroll
        for (int mt = 0; mt < 2; mt++) {
            const int r0 = wm * 32 + mt * 16 + gid;
            #pragma unroll
            for (int nt = 0; nt < 4; nt++) {
                const int cl = wn * 32 + nt * 8 + 2 * tig;
                __half2 h0 = __floats2half2_rn(ex2f(c[mt][nt][0]) * inv[mt][0],
                                               ex2f(c[mt][nt][1]) * inv[mt][0]);
                __half2 h1 = __floats2half2_rn(ex2f(c[mt][nt][2]) * inv[mt][1],
                                               ex2f(c[mt][nt][3]) * inv[mt][1]);
                *(unsigned*)&Ps[r0 * PSP + cl]       = *(unsigned*)&h0;
                *(unsigned*)&Ps[(r0 + 8) * PSP + cl] = *(unsigned*)&h1;
            }
        }
        __syncthreads();

        #pragma unroll
        for (int kk = 0; kk < 128; kk += 16) {
            unsigned af[2][4], bf[4];
            ldsm4(af[0], PsU + ((wm * 32 + arow) * PSP + kk + acolh) * 2);
            ldsm4(af[1], PsU + ((wm * 32 + 16 + arow) * PSP + kk + acolh) * 2);
            ldsm4t(bf, vcur + ((kk + arow) * VSP + wn * 16 + acolh) * 2);
            #pragma unroll
            for (int mt = 0; mt < 2; mt++) {
                mma_fp16(cacc[mt][0], af[mt], bf[0], bf[1]);
                mma_fp16(cacc[mt][1], af[mt], bf[2], bf[3]);
            }
        }

        if (WRITE_ATTN) {
            #pragma unroll
            for (int i = 0; i < 8; i++) {
                const int idx = tid + i * 256;
                const int row = idx >> 5, c4 = idx & 31;
                const uint2 hraw = *(const uint2*)&Ps[row * PSP + c4 * 4];
                const float2 f01 = __half22float2(*(const __half2*)&hraw.x);
                const float2 f23 = __half22float2(*(const __half2*)&hraw.y);
                *(float4*)(attp + (size_t)row * SS + kt * 128 + c4 * 4) =
                    make_float4(f01.x, f01.y, f23.x, f23.y);
            }
        }
        __syncthreads();
    }

    __half* cp = ctx + base + (size_t)q0 * DD;
    #pragma unroll
    for (int mt = 0; mt < 2; mt++) {
        const int r0 = wm * 32 + mt * 16 + gid;
        #pragma unroll
        for (int nt = 0; nt < 2; nt++) {
            const int cl = wn * 16 + nt * 8 + 2 * tig;
            __half2 h0 = __floats2half2_rn(cacc[mt][nt][0], cacc[mt][nt][1]);
            __half2 h1 = __floats2half2_rn(cacc[mt][nt][2], cacc[mt][nt][3]);
            *(unsigned*)(cp + (size_t)r0 * DD + cl)       = *(unsigned*)&h0;
            *(unsigned*)(cp + (size_t)(r0 + 8) * DD + cl) = *(unsigned*)&h1;
        }
    }
}

// ===========================================================================
// Fused QKV projection: one launch over the stacked [3072 x 1024] weight.
// Grid.x covers N=3*DD; each 128-col tile routes to q/k/v by segment, with
// the EXS scale applied to the Q segment. Same pipeline as gemm_h.
// ===========================================================================
#define GSP 72
#define GTILE (128 * GSP)
#define GEMM_SMEM_BYTES (4 * GTILE * 2)

__global__ __launch_bounds__(256, 2) void gemm_qkv(
    const __half* __restrict__ A, const __half* __restrict__ Bm,
    __half* __restrict__ qo, __half* __restrict__ ko, __half* __restrict__ vo)
{
    extern __shared__ __half gsm[];
    const unsigned smu = (unsigned)__cvta_generic_to_shared(gsm);
    const unsigned AsU = smu;
    const unsigned BsU = smu + 2 * GTILE * 2;

    const int tid = threadIdx.x;
    const int warp = tid >> 5, l = tid & 31;
    const int gid = l >> 2, tig = l & 3;
    const int wm = warp >> 1, wn = warp & 1;
    const int m0 = blockIdx.y * 128;
    const int n0g = blockIdx.x * 128;          // 0..3071 (stacked N)
    const int seg = n0g >> 10;                 // 0=Q, 1=K, 2=V
    const int n0 = n0g & 1023;                 // column within segment

    __half* C = (seg == 0) ? qo : (seg == 1) ? ko : vo;
    const float scale = (seg == 0) ? EXS : 1.0f;

    const int arow  = (l & 7) + ((l >> 3) & 1) * 8;
    const int acolh = (l >> 4) * 8;

    const int crow0 = tid >> 3, cch = (tid & 7) * 8;

    float acc[2][8][4] = {};

    #pragma unroll
    for (int i = 0; i < 4; i++) {
        const int row = crow0 + i * 32;
        CP_A16(AsU + (row * GSP + cch) * 2, A  + (size_t)(m0 + row) * DD + cch);
        CP_A16(BsU + (row * GSP + cch) * 2, Bm + (size_t)(n0g + row) * DD + cch);
    }
    CP_COMMIT();

    for (int it = 0; it < DD / 64; it++) {
        if (it < DD / 64 - 1) {
            const unsigned ab = AsU + ((it + 1) & 1) * GTILE * 2;
            const unsigned bb = BsU + ((it + 1) & 1) * GTILE * 2;
            const int k0 = (it + 1) * 64;
            #pragma unroll
            for (int i = 0; i < 4; i++) {
                const int row = crow0 + i * 32;
                CP_A16(ab + (row * GSP + cch) * 2, A  + (size_t)(m0 + row) * DD + k0 + cch);
                CP_A16(bb + (row * GSP + cch) * 2, Bm + (size_t)(n0g + row) * DD + k0 + cch);
            }
            CP_COMMIT();
            CP_WAIT1();
        } else {
            CP_WAIT0();
        }
        __syncthreads();

        const unsigned acur = AsU + (it & 1) * GTILE * 2;
        const unsigned bcur = BsU + (it & 1) * GTILE * 2;

        #pragma unroll
        for (int kk = 0; kk < 64; kk += 16) {
            unsigned af[2][4], bf[4][4];
            ldsm4(af[0], acur + ((wm * 32 + arow) * GSP + kk + acolh) * 2);
            ldsm4(af[1], acur + ((wm * 32 + 16 + arow) * GSP + kk + acolh) * 2);
            #pragma unroll
            for (int p = 0; p < 4; p++)
                ldsm4(bf[p], bcur + ((wn * 64 + p * 16 + arow) * GSP + kk + acolh) * 2);
            #pragma unroll
            for (int mt = 0; mt < 2; mt++)
                #pragma unroll
                for (int p = 0; p < 4; p++) {
                    mma_fp16(acc[mt][p * 2],     af[mt], bf[p][0], bf[p][2]);
                    mma_fp16(acc[mt][p * 2 + 1], af[mt], bf[p][1], bf[p][3]);
                }
        }
        __syncthreads();
    }

    #pragma unroll
    for (int mt = 0; mt < 2; mt++) {
        #pragma unroll
        for (int nt = 0; nt < 8; nt++) {
            const int r0 = m0 + wm * 32 + mt * 16 + gid;
            const int cc = n0 + wn * 64 + nt * 8 + tig * 2;
            __half2 h0 = __floats2half2_rn(acc[mt][nt][0] * scale, acc[mt][nt][1] * scale);
            __half2 h1 = __floats2half2_rn(acc[mt][nt][2] * scale, acc[mt][nt][3] * scale);
            *(unsigned*)(C + (size_t)r0 * DD + cc)       = *(unsigned*)&h0;
            *(unsigned*)(C + (size_t)(r0 + 8) * DD + cc) = *(unsigned*)&h1;
        }
    }
}

// ===========================================================================
// Output projection GEMM (fp16 in, fp32 out), same pipeline.
// ===========================================================================
__global__ __launch_bounds__(256, 2) void gemm_o(
    const __half* __restrict__ A, const __half* __restrict__ Bm, float* __restrict__ C)
{
    extern __shared__ __half gsm[];
    const unsigned smu = (unsigned)__cvta_generic_to_shared(gsm);
    const unsigned AsU = smu;
    const unsigned BsU = smu + 2 * GTILE * 2;

    const int tid = threadIdx.x;
    const int warp = tid >> 5, l = tid & 31;
    const int gid = l >> 2, tig = l & 3;
    const int wm = warp >> 1, wn = warp & 1;
    const int m0 = blockIdx.y * 128;
    const int n0 = blockIdx.x * 128;

    const int arow  = (l & 7) + ((l >> 3) & 1) * 8;
    const int acolh = (l >> 4) * 8;

    const int crow0 = tid >> 3, cch = (tid & 7) * 8;

    float acc[2][8][4] = {};

    #pragma unroll
    for (int i = 0; i < 4; i++) {
        const int row = crow0 + i * 32;
        CP_A16(AsU + (row * GSP + cch) * 2, A  + (size_t)(m0 + row) * DD + cch);
        CP_A16(BsU + (row * GSP + cch) * 2, Bm + (size_t)(n0 + row) * DD + cch);
    }
    CP_COMMIT();

    for (int it = 0; it < DD / 64; it++) {
        if (it < DD / 64 - 1) {
            const unsigned ab = AsU + ((it + 1) & 1) * GTILE * 2;
            const unsigned bb = BsU + ((it + 1) & 1) * GTILE * 2;
            const int k0 = (it + 1) * 64;
            #pragma unroll
            for (int i = 0; i < 4; i++) {
                const int row = crow0 + i * 32;
                CP_A16(ab + (row * GSP + cch) * 2, A  + (size_t)(m0 + row) * DD + k0 + cch);
                CP_A16(bb + (row * GSP + cch) * 2, Bm + (size_t)(n0 + row) * DD + k0 + cch);
            }
            CP_COMMIT();
            CP_WAIT1();
        } else {
            CP_WAIT0();
        }
        __syncthreads();

        const unsigned acur = AsU + (it & 1) * GTILE * 2;
        const unsigned bcur = BsU + (it & 1) * GTILE * 2;

        #pragma unroll
        for (int kk = 0; kk < 64; kk += 16) {
            unsigned af[2][4], bf[4][4];
            ldsm4(af[0], acur + ((wm * 32 + arow) * GSP + kk + acolh) * 2);
            ldsm4(af[1], acur + ((wm * 32 + 16 + arow) * GSP + kk + acolh) * 2);
            #pragma unroll
            for (int p = 0; p < 4; p++)
                ldsm4(bf[p], bcur + ((wn * 64 + p * 16 + arow) * GSP + kk + acolh) * 2);
            #pragma unroll
            for (int mt = 0; mt < 2; mt++)
                #pragma unroll
                for (int p = 0; p < 4; p++) {
                    mma_fp16(acc[mt][p * 2],     af[mt], bf[p][0], bf[p][2]);
                    mma_fp16(acc[mt][p * 2 + 1], af[mt], bf[p][1], bf[p][3]);
                }
        }
        __syncthreads();
    }

    #pragma unroll
    for (int mt = 0; mt < 2; mt++) {
        #pragma unroll
        for (int nt = 0; nt < 8; nt++) {
            const int r0 = m0 + wm * 32 + mt * 16 + gid;
            const int cc = n0 + wn * 64 + nt * 8 + tig * 2;
            *(float2*)(C + (size_t)r0 * DD + cc)       = make_float2(acc[mt][nt][0], acc[mt][nt][1]);
            *(float2*)(C + (size_t)(r0 + 8) * DD + cc) = make_float2(acc[mt][nt][2], acc[mt][nt][3]);
        }
    }
}

// ---------------------------------------------------------------------------
// Fused bias + residual + LayerNorm (float4 vectorized).
// ---------------------------------------------------------------------------
__global__ __launch_bounds__(256) void ln_kernel(
    const float* __restrict__ po, const float* __restrict__ x,
    const float* __restrict__ bo, const float* __restrict__ gamma,
    const float* __restrict__ beta, float* __restrict__ y)
{
    const size_t row = blockIdx.x;
    const int t = threadIdx.x;
    const int c = t * 4;

    const float4 p4 = *(const float4*)(po + row * DD + c);
    const float4 x4 = *(const float4*)(x  + row * DD + c);
    const float4 b4 = *(const float4*)(bo + c);

    float4 u;
    u.x = p4.x + b4.x + x4.x;
    u.y = p4.y + b4.y + x4.y;
    u.z = p4.z + b4.z + x4.z;
    u.w = p4.w + b4.w + x4.w;

    float s  = u.x + u.y + u.z + u.w;
    float s2 = u.x * u.x + u.y * u.y + u.z * u.z + u.w * u.w;

    __shared__ float r1[8], r2[8];
    #pragma unroll
    for (int o = 16; o; o >>= 1) {
        s  += __shfl_xor_sync(0xffffffffu, s, o);
        s2 += __shfl_xor_sync(0xffffffffu, s2, o);
    }
    if ((t & 31) == 0) { r1[t >> 5] = s; r2[t >> 5] = s2; }
    __syncthreads();
    s = r1[0]; s2 = r2[0];
    #pragma unroll
    for (int i = 1; i < 8; i++) { s += r1[i]; s2 += r2[i]; }

    const float mu = s * (1.0f / DD);
    const float var = s2 * (1.0f / DD) - mu * mu;
    const float inv = rsqrtf(var + 1e-5f);

    const float4 g4 = *(const float4*)(gamma + c);
    const float4 be4 = *(const float4*)(beta + c);
    float4 o4;
    o4.x = (u.x - mu) * inv * g4.x + be4.x;
    o4.y = (u.y - mu) * inv * g4.y + be4.y;
    o4.z = (u.z - mu) * inv * g4.z + be4.z;
    o4.w = (u.w - mu) * inv * g4.w + be4.w;
    *(float4*)(y + row * DD + c) = o4;
}

// ---------------------------------------------------------------------------
extern "C" void kernel_launch(void* const* d_in, const int* in_sizes, int n_in,
                              void* d_out, int out_size)
{
    const float* x     = (const float*)d_in[0];
    const float* Wq    = (const float*)d_in[1];
    const float* Wk    = (const float*)d_in[2];
    const float* Wv    = (const float*)d_in[3];
    const float* Wo    = (const float*)d_in[4];
    const float* bo    = (const float*)d_in[5];
    const float* gamma = (const float*)d_in[6];
    const float* beta  = (const float*)d_in[7];

    __half *xh, *wh, *q, *k, *v, *ctx;
    float *po, *attn_scratch;
    cudaGetSymbolAddress((void**)&xh,  g_xh);
    cudaGetSymbolAddress((void**)&wh,  g_wh);
    cudaGetSymbolAddress((void**)&q,   g_q);
    cudaGetSymbolAddress((void**)&k,   g_k);
    cudaGetSymbolAddress((void**)&v,   g_v);
    cudaGetSymbolAddress((void**)&ctx, g_ctx);
    cudaGetSymbolAddress((void**)&po,  g_po);
    cudaGetSymbolAddress((void**)&attn_scratch, g_attn);

    const size_t Y   = (size_t)BB * SS * DD;
    const size_t ATT = (size_t)BB * HH * SS * SS;
    const size_t W   = (size_t)DD * DD;

    float* yout = (float*)d_out;
    const bool want_attn = ((size_t)out_size >= Y + ATT);
    float* attn = want_attn ? (yout + Y) : attn_scratch;

    const dim3 blk(256);

    // one combined fp32 -> fp16 conversion launch
    const int n4tot = N4X + 4 * N4W;
    f2h_multi<<<(n4tot + 255) / 256, blk>>>((const float4*)x, (const float4*)Wq,
                                            (const float4*)Wk, (const float4*)Wv,
                                            (const float4*)Wo, (uint2*)xh, (uint2*)wh);

    // fused Q/K/V projection: one launch, N = 3*DD over stacked weights
    cudaFuncSetAttribute(gemm_qkv, cudaFuncAttributeMaxDynamicSharedMemorySize, GEMM_SMEM_BYTES);
    cudaFuncSetAttribute(gemm_o,   cudaFuncAttributeMaxDynamicSharedMemorySize, GEMM_SMEM_BYTES);
    const dim3 gqkv(3 * DD / 128, (BB * SS) / 128, 1);
    gemm_qkv<<<gqkv, blk, GEMM_SMEM_BYTES>>>(xh, wh, q, k, v);

    // fused attention
    const dim3 gatt(SS / 64, BB * HH);
    if (want_attn) {
        cudaFuncSetAttribute(attn_kernel<true>, cudaFuncAttributeMaxDynamicSharedMemorySize, SM_BYTES);
        attn_kernel<true><<<gatt, 256, SM_BYTES>>>(q, k, v, attn, ctx);
    } else {
        cudaFuncSetAttribute(attn_kernel<false>, cudaFuncAttributeMaxDynamicSharedMemorySize, SM_BYTES);
        attn_kernel<false><<<gatt, 256, SM_BYTES>>>(q, k, v, attn, ctx);
    }

    // output projection (fp16 in, fp32 out)
    const dim3 gproj(DD / 128, (BB * SS) / 128, 1);
    gemm_o<<<gproj, blk, GEMM_SMEM_BYTES>>>(ctx, wh + 3 * W, po);

    // bias + residual + LayerNorm -> y
    ln_kernel<<<BB * SS, blk>>>(po, x, bo, gamma, beta, yout);
}